// round 2
// baseline (speedup 1.0000x reference)
#include <cuda_runtime.h>
#include <cstdint>

#define NMAX 100000
#define EPSV 1e-5f

typedef unsigned long long ull;

// 16 floats per node: [0..7] = b0 + x@W0_top, [8..15] = x@W0_bot
__device__ float g_nodefeat[NMAX * 16];
__device__ int g_idx_is64;

// ---------------- f32x2 / MUFU helpers ----------------
__device__ __forceinline__ ull pk(float lo, float hi) {
    ull d; asm("mov.b64 %0, {%1, %2};" : "=l"(d) : "f"(lo), "f"(hi)); return d;
}
__device__ __forceinline__ ull pkdup(float v) {
    ull d; asm("mov.b64 %0, {%1, %1};" : "=l"(d) : "f"(v)); return d;
}
__device__ __forceinline__ void upk(ull v, float& lo, float& hi) {
    asm("mov.b64 {%0, %1}, %2;" : "=f"(lo), "=f"(hi) : "l"(v));
}
__device__ __forceinline__ ull add2(ull a, ull b) {
    ull d; asm("add.rn.f32x2 %0, %1, %2;" : "=l"(d) : "l"(a), "l"(b)); return d;
}
__device__ __forceinline__ ull mul2(ull a, ull b) {
    ull d; asm("mul.rn.f32x2 %0, %1, %2;" : "=l"(d) : "l"(a), "l"(b)); return d;
}
__device__ __forceinline__ ull fma2(ull a, ull b, ull c) {
    ull d; asm("fma.rn.f32x2 %0, %1, %2, %3;" : "=l"(d) : "l"(a), "l"(b), "l"(c)); return d;
}
__device__ __forceinline__ float ex2f_(float x) {
    float r; asm("ex2.approx.f32 %0, %1;" : "=f"(r) : "f"(x)); return r;
}
__device__ __forceinline__ float rcpf_(float x) {
    float r; asm("rcp.approx.f32 %0, %1;" : "=f"(r) : "f"(x)); return r;
}
__device__ __forceinline__ float rsqf_(float x) {
    float r; asm("rsqrt.approx.f32 %0, %1;" : "=f"(r) : "f"(x)); return r;
}

// ---------------- math blocks ----------------

// LayerNorm over 8 values held as 4 f32x2 pairs. y = (h-m)*rsqrt(v+eps)*g + be
__device__ __forceinline__ void ln8(ull h[4], const float* __restrict__ g,
                                    const float* __restrict__ be) {
    ull s = add2(add2(h[0], h[1]), add2(h[2], h[3]));
    float sl, sh; upk(s, sl, sh);
    float m = (sl + sh) * 0.125f;

    ull q = mul2(h[0], h[0]);
    q = fma2(h[1], h[1], q);
    q = fma2(h[2], h[2], q);
    q = fma2(h[3], h[3], q);
    float ql, qh; upk(q, ql, qh);
    float msq = (ql + qh) * 0.125f;
    float mm = m * m;
    float var = msq - mm;
    float sc = rsqf_(var + EPSV);

    ull sc2 = pkdup(sc);
    ull nm2 = pkdup(-m);
    const ull* gp = reinterpret_cast<const ull*>(g);
    const ull* bp = reinterpret_cast<const ull*>(be);
#pragma unroll
    for (int p = 0; p < 4; p++) {
        ull ag = mul2(sc2, gp[p]);        // s * g
        ull c  = fma2(nm2, ag, bp[p]);    // be - m*s*g
        h[p]   = fma2(h[p], ag, c);       // h*s*g + (be - m*s*g)
    }
}

// tanh on a f32x2 pair: tanh(x) = (e^{2x}-1)/(e^{2x}+1)
// via ex2.approx + rcp.approx  (~1e-6 error; |x| <= ~2.65 post-LN so no overflow)
__device__ __forceinline__ ull tanh2(ull p) {
    const ull K2   = pkdup(2.8853900817779268f);  // 2*log2(e)
    const ull ONE2 = pkdup(1.0f);
    const ull NEG2 = pkdup(-1.0f);
    ull xs = mul2(p, K2);
    float a, b; upk(xs, a, b);
    ull tp = pk(ex2f_(a), ex2f_(b));
    ull num = add2(tp, NEG2);
    ull den = add2(tp, ONE2);
    float dl, dh; upk(den, dl, dh);
    ull rp = pk(rcpf_(dl), rcpf_(dh));
    return mul2(num, rp);
}

__device__ __forceinline__ void tanh8(ull h[4]) {
#pragma unroll
    for (int p = 0; p < 4; p++) h[p] = tanh2(h[p]);
}

// out[8] = h[8] @ W(8x8, row-major) + bias
__device__ __forceinline__ void mm8(const ull h[4], const float* __restrict__ W,
                                    const float* __restrict__ bias, ull out[4]) {
    const ull* bp = reinterpret_cast<const ull*>(bias);
#pragma unroll
    for (int p = 0; p < 4; p++) out[p] = bp[p];
    float hs[8];
#pragma unroll
    for (int p = 0; p < 4; p++) upk(h[p], hs[2 * p], hs[2 * p + 1]);
#pragma unroll
    for (int k = 0; k < 8; k++) {
        ull hk = pkdup(hs[k]);
        const ull* wr = reinterpret_cast<const ull*>(W + 8 * k);
#pragma unroll
        for (int p = 0; p < 4; p++) out[p] = fma2(hk, wr[p], out[p]);
    }
}

// ---------------- kernel 0: edge_index dtype detection ----------------
// If the buffer is int32, an int64 view packs two random node indices per
// word -> value >= N with overwhelming probability across 256 samples.
__global__ void detect_dtype(const void* __restrict__ ei, int N) {
    const long long* p = (const long long*)ei;
    int is64 = 1;
    for (int i = 0; i < 256; i++) {
        long long v = p[i];
        if (v < 0 || v >= (long long)N) { is64 = 0; break; }
    }
    g_idx_is64 = is64;
}

// ---------------- kernel 1: per-node precompute ----------------
// top[j] = b0[j] + sum_k x[n][k] * W0[k][j]   (k = 0..2)
// bot[j] =         sum_k x[n][k] * W0[3+k][j]
__global__ void node_prep(const float* __restrict__ x, const float* __restrict__ W0,
                          const float* __restrict__ b0, int N) {
    int n = blockIdx.x * blockDim.x + threadIdx.x;
    if (n >= N) return;
    float x0 = x[n * 3 + 0], x1 = x[n * 3 + 1], x2 = x[n * 3 + 2];
    float t[16];
#pragma unroll
    for (int j = 0; j < 8; j++) {
        t[j]     = b0[j] + x0 * W0[j] + x1 * W0[8 + j] + x2 * W0[16 + j];
        t[8 + j] =         x0 * W0[24 + j] + x1 * W0[32 + j] + x2 * W0[40 + j];
    }
    float4* dst = reinterpret_cast<float4*>(g_nodefeat + (size_t)n * 16);
#pragma unroll
    for (int q = 0; q < 4; q++)
        dst[q] = make_float4(t[4 * q], t[4 * q + 1], t[4 * q + 2], t[4 * q + 3]);
}

// ---------------- kernel 2: per-edge MLP ----------------
// smem layout (floats): W1 @0, W2 @64, b1 @128, g1 @136, be1 @144,
//                       b2 @152, g2 @160, be2 @168, W3 @176, g0 @184, be0 @192, b3 @200
__global__ __launch_bounds__(256)
void edge_kernel(const void* __restrict__ ei_raw,
                 const float* __restrict__ W1, const float* __restrict__ b1,
                 const float* __restrict__ g1, const float* __restrict__ be1,
                 const float* __restrict__ W2, const float* __restrict__ b2,
                 const float* __restrict__ g2, const float* __restrict__ be2,
                 const float* __restrict__ W3, const float* __restrict__ b3,
                 const float* __restrict__ g0, const float* __restrict__ be0,
                 float* __restrict__ out, int E) {
    __shared__ __align__(16) float sm[208];
    int t = threadIdx.x;
    if (t < 64) {
        sm[t] = W1[t];
    } else if (t < 128) {
        sm[64 + (t - 64)] = W2[t - 64];
    } else if (t < 208) {
        int i = t - 128, grp = i >> 3, j = i & 7;
        float v;
        switch (grp) {
            case 0: v = b1[j];  break;
            case 1: v = g1[j];  break;
            case 2: v = be1[j]; break;
            case 3: v = b2[j];  break;
            case 4: v = g2[j];  break;
            case 5: v = be2[j]; break;
            case 6: v = W3[j];  break;
            case 7: v = g0[j];  break;
            case 8: v = be0[j]; break;
            default: v = (j == 0) ? b3[0] : 0.0f; break;
        }
        sm[128 + i] = v;
    }
    __syncthreads();

    int e = blockIdx.x * blockDim.x + threadIdx.x;
    if (e >= E) return;

    int s, d;
    if (g_idx_is64) {
        const long long* ei = (const long long*)ei_raw;
        s = (int)ei[e];
        d = (int)ei[E + e];
    } else {
        const int* ei = (const int*)ei_raw;
        s = ei[e];
        d = ei[E + e];
    }

    const ulonglong2* nf = reinterpret_cast<const ulonglong2*>(g_nodefeat);
    ulonglong2 a0 = nf[s * 4 + 0];
    ulonglong2 a1 = nf[s * 4 + 1];
    ulonglong2 c0 = nf[d * 4 + 2];
    ulonglong2 c1 = nf[d * 4 + 3];

    ull h[4];
    h[0] = add2(a0.x, c0.x);
    h[1] = add2(a0.y, c0.y);
    h[2] = add2(a1.x, c1.x);
    h[3] = add2(a1.y, c1.y);

    ln8(h, sm + 184, sm + 192);   // g0, be0
    tanh8(h);

    ull h2[4];
    mm8(h, sm + 0, sm + 128, h2); // W1, b1
    ln8(h2, sm + 136, sm + 144);  // g1, be1
    tanh8(h2);

    ull h3[4];
    mm8(h2, sm + 64, sm + 152, h3); // W2, b2
    ln8(h3, sm + 160, sm + 168);    // g2, be2
    tanh8(h3);

    const ull* w3 = reinterpret_cast<const ull*>(sm + 176);
    ull acc = mul2(h3[0], w3[0]);
    acc = fma2(h3[1], w3[1], acc);
    acc = fma2(h3[2], w3[2], acc);
    acc = fma2(h3[3], w3[3], acc);
    float lo, hi; upk(acc, lo, hi);
    out[e] = lo + hi + sm[200];
}

// ---------------- launch ----------------
extern "C" void kernel_launch(void* const* d_in, const int* in_sizes, int n_in,
                              void* d_out, int out_size) {
    const float* x   = (const float*)d_in[0];
    const void*  ei  = (const void*)d_in[1];
    const float* W0  = (const float*)d_in[2];
    const float* b0  = (const float*)d_in[3];
    const float* g0  = (const float*)d_in[4];
    const float* be0 = (const float*)d_in[5];
    const float* W1  = (const float*)d_in[6];
    const float* b1  = (const float*)d_in[7];
    const float* g1  = (const float*)d_in[8];
    const float* be1 = (const float*)d_in[9];
    const float* W2  = (const float*)d_in[10];
    const float* b2  = (const float*)d_in[11];
    const float* g2  = (const float*)d_in[12];
    const float* be2 = (const float*)d_in[13];
    const float* W3  = (const float*)d_in[14];
    const float* b3  = (const float*)d_in[15];
    float* out = (float*)d_out;

    int N = in_sizes[0] / 3;
    if (N > NMAX) N = NMAX;
    int E = in_sizes[1] / 2;

    detect_dtype<<<1, 1>>>(ei, N);
    node_prep<<<(N + 255) / 256, 256>>>(x, W0, b0, N);
    edge_kernel<<<(E + 255) / 256, 256>>>(ei, W1, b1, g1, be1, W2, b2, g2, be2,
                                          W3, b3, g0, be0, out, E);
}

// round 5
// speedup vs baseline: 1.0182x; 1.0182x over previous
#include <cuda_runtime.h>
#include <cstdint>

#define NMAX 100000
#define EPSV 1e-5f
#define KTAN 2.885390081777927f   // 2*log2(e)

typedef unsigned long long ull;

// 16 floats per node: [0..7] = b0 + x@W0_top, [8..15] = x@W0_bot
__device__ float g_nodefeat[NMAX * 16];
__device__ int g_idx_is64;

// ---------------- f32x2 / MUFU helpers ----------------
__device__ __forceinline__ ull pkdup(float v) {
    ull d; asm("mov.b64 %0, {%1, %1};" : "=l"(d) : "f"(v)); return d;
}
__device__ __forceinline__ void upk(ull v, float& lo, float& hi) {
    asm("mov.b64 {%0, %1}, %2;" : "=f"(lo), "=f"(hi) : "l"(v));
}
__device__ __forceinline__ ull add2(ull a, ull b) {
    ull d; asm("add.rn.f32x2 %0, %1, %2;" : "=l"(d) : "l"(a), "l"(b)); return d;
}
__device__ __forceinline__ ull mul2(ull a, ull b) {
    ull d; asm("mul.rn.f32x2 %0, %1, %2;" : "=l"(d) : "l"(a), "l"(b)); return d;
}
__device__ __forceinline__ ull fma2(ull a, ull b, ull c) {
    ull d; asm("fma.rn.f32x2 %0, %1, %2, %3;" : "=l"(d) : "l"(a), "l"(b), "l"(c)); return d;
}
__device__ __forceinline__ float ex2f_(float x) {
    float r; asm("ex2.approx.f32 %0, %1;" : "=f"(r) : "f"(x)); return r;
}
__device__ __forceinline__ float rcpf_(float x) {
    float r; asm("rcp.approx.f32 %0, %1;" : "=f"(r) : "f"(x)); return r;
}
__device__ __forceinline__ float rsqf_(float x) {
    float r; asm("rsqrt.approx.f32 %0, %1;" : "=f"(r) : "f"(x)); return r;
}

// ---------------- math blocks ----------------

// LayerNorm over 8 packed values, emitting 8 SCALARS pre-scaled by KTAN:
//   u = K * ((h - m) * rsqrt(var+eps) * g + be)
// beK in smem already holds K*be; K is folded into sc.
__device__ __forceinline__ void ln8k(const ull h[4], const float* __restrict__ g,
                                     const float* __restrict__ beK, float u[8]) {
    ull s = add2(add2(h[0], h[1]), add2(h[2], h[3]));
    float sl, sh; upk(s, sl, sh);
    float m = (sl + sh) * 0.125f;

    ull q = mul2(h[0], h[0]);
    q = fma2(h[1], h[1], q);
    q = fma2(h[2], h[2], q);
    q = fma2(h[3], h[3], q);
    float ql, qh; upk(q, ql, qh);
    float msq = (ql + qh) * 0.125f;
    float var = fmaf(-m, m, msq);
    float sc = KTAN * rsqf_(var + EPSV);

    ull sc2 = pkdup(sc);
    ull nm2 = pkdup(-m);
    const ull* gp = reinterpret_cast<const ull*>(g);
    const ull* bp = reinterpret_cast<const ull*>(beK);
#pragma unroll
    for (int p = 0; p < 4; p++) {
        ull ag = mul2(sc2, gp[p]);        // K * s * g
        ull c  = fma2(nm2, ag, bp[p]);    // K*be - m*K*s*g
        ull r  = fma2(h[p], ag, c);       // K * ln(h)
        upk(r, u[2 * p], u[2 * p + 1]);
    }
}

// tanh from pre-scaled arg u = 2x*log2(e):
//   tanh(x) = 1 - 2/(e^{2x}+1) = 1 - 2*rcp(ex2(u)+1)
// 2 fma-pipe ops + 2 MUFU per scalar, no packing.
__device__ __forceinline__ void tanh8s(const float u[8], float y[8]) {
#pragma unroll
    for (int i = 0; i < 8; i++) {
        float t = ex2f_(u[i]);
        float r = rcpf_(t + 1.0f);
        y[i] = fmaf(-2.0f, r, 1.0f);
    }
}

// out[8] (packed) = hs[8] @ W(8x8 row-major) + bias
__device__ __forceinline__ void mm8s(const float hs[8], const float* __restrict__ W,
                                     const float* __restrict__ bias, ull out[4]) {
    const ull* bp = reinterpret_cast<const ull*>(bias);
#pragma unroll
    for (int p = 0; p < 4; p++) out[p] = bp[p];
#pragma unroll
    for (int k = 0; k < 8; k++) {
        ull hk = pkdup(hs[k]);
        const ull* wr = reinterpret_cast<const ull*>(W + 8 * k);
#pragma unroll
        for (int p = 0; p < 4; p++) out[p] = fma2(hk, wr[p], out[p]);
    }
}

// ---------------- kernel 1: node precompute + dtype detection ----------------
// top[j] = b0[j] + x@W0_top ; bot[j] = x@W0_bot
// Block 0 additionally samples 256 int64-view values of edge_index: if the
// buffer is int32, a 64-bit view packs two random indices per word -> value
// >= N with prob ~1-1e-5 per sample; all-256-pass misdetect is ~impossible.
__global__ void node_prep(const float* __restrict__ x, const float* __restrict__ W0,
                          const float* __restrict__ b0, const void* __restrict__ ei,
                          int N) {
    __shared__ int s_ok;
    if (blockIdx.x == 0) {
        if (threadIdx.x == 0) s_ok = 1;
        __syncthreads();
        long long v = ((const long long*)ei)[threadIdx.x];
        if (v < 0 || v >= (long long)N) s_ok = 0;   // benign race: all write 0
        __syncthreads();
        if (threadIdx.x == 0) g_idx_is64 = s_ok;
    }

    int n = blockIdx.x * blockDim.x + threadIdx.x;
    if (n >= N) return;
    float x0 = x[n * 3 + 0], x1 = x[n * 3 + 1], x2 = x[n * 3 + 2];
    float t[16];
#pragma unroll
    for (int j = 0; j < 8; j++) {
        t[j]     = b0[j] + x0 * W0[j] + x1 * W0[8 + j] + x2 * W0[16 + j];
        t[8 + j] =         x0 * W0[24 + j] + x1 * W0[32 + j] + x2 * W0[40 + j];
    }
    float4* dst = reinterpret_cast<float4*>(g_nodefeat + (size_t)n * 16);
#pragma unroll
    for (int q = 0; q < 4; q++)
        dst[q] = make_float4(t[4 * q], t[4 * q + 1], t[4 * q + 2], t[4 * q + 3]);
}

// ---------------- kernel 2: per-edge MLP ----------------
// smem layout (floats): W1 @0, W2 @64, b1 @128, g1 @136, K*be1 @144,
//   b2 @152, g2 @160, K*be2 @168, W3 @176, g0 @184, K*be0 @192, b3 @200
__global__ __launch_bounds__(256)
void edge_kernel(const void* __restrict__ ei_raw,
                 const float* __restrict__ W1, const float* __restrict__ b1,
                 const float* __restrict__ g1, const float* __restrict__ be1,
                 const float* __restrict__ W2, const float* __restrict__ b2,
                 const float* __restrict__ g2, const float* __restrict__ be2,
                 const float* __restrict__ W3, const float* __restrict__ b3,
                 const float* __restrict__ g0, const float* __restrict__ be0,
                 float* __restrict__ out, int E) {
    __shared__ __align__(16) float sm[208];
    int t = threadIdx.x;
    if (t < 64) {
        sm[t] = W1[t];
    } else if (t < 128) {
        sm[64 + (t - 64)] = W2[t - 64];
    } else if (t < 208) {
        int i = t - 128, grp = i >> 3, j = i & 7;
        float v;
        switch (grp) {
            case 0: v = b1[j];          break;
            case 1: v = g1[j];          break;
            case 2: v = KTAN * be1[j];  break;
            case 3: v = b2[j];          break;
            case 4: v = g2[j];          break;
            case 5: v = KTAN * be2[j];  break;
            case 6: v = W3[j];          break;
            case 7: v = g0[j];          break;
            case 8: v = KTAN * be0[j];  break;
            default: v = (j == 0) ? b3[0] : 0.0f; break;
        }
        sm[128 + i] = v;
    }
    __syncthreads();

    int e = blockIdx.x * blockDim.x + threadIdx.x;
    if (e >= E) return;

    int s, d;
    if (g_idx_is64) {
        const long long* ei = (const long long*)ei_raw;
        s = (int)ei[e];
        d = (int)ei[E + e];
    } else {
        const int* ei = (const int*)ei_raw;
        s = ei[e];
        d = ei[E + e];
    }

    const ulonglong2* nf = reinterpret_cast<const ulonglong2*>(g_nodefeat);
    ulonglong2 a0 = nf[s * 4 + 0];
    ulonglong2 a1 = nf[s * 4 + 1];
    ulonglong2 c0 = nf[d * 4 + 2];
    ulonglong2 c1 = nf[d * 4 + 3];

    ull h[4];
    h[0] = add2(a0.x, c0.x);
    h[1] = add2(a0.y, c0.y);
    h[2] = add2(a1.x, c1.x);
    h[3] = add2(a1.y, c1.y);

    float u[8], y[8];
    ln8k(h, sm + 184, sm + 192, u);   // g0, K*be0
    tanh8s(u, y);

    ull h2[4];
    mm8s(y, sm + 0, sm + 128, h2);    // W1, b1
    ln8k(h2, sm + 136, sm + 144, u);  // g1, K*be1
    tanh8s(u, y);

    ull h3[4];
    mm8s(y, sm + 64, sm + 152, h3);   // W2, b2
    ln8k(h3, sm + 160, sm + 168, u);  // g2, K*be2
    tanh8s(u, y);

    float acc = sm[200];              // b3
#pragma unroll
    for (int i = 0; i < 8; i++) acc = fmaf(y[i], sm[176 + i], acc);
    out[e] = acc;
}

// ---------------- launch ----------------
extern "C" void kernel_launch(void* const* d_in, const int* in_sizes, int n_in,
                              void* d_out, int out_size) {
    const float* x   = (const float*)d_in[0];
    const void*  ei  = (const void*)d_in[1];
    const float* W0  = (const float*)d_in[2];
    const float* b0  = (const float*)d_in[3];
    const float* g0  = (const float*)d_in[4];
    const float* be0 = (const float*)d_in[5];
    const float* W1  = (const float*)d_in[6];
    const float* b1  = (const float*)d_in[7];
    const float* g1  = (const float*)d_in[8];
    const float* be1 = (const float*)d_in[9];
    const float* W2  = (const float*)d_in[10];
    const float* b2  = (const float*)d_in[11];
    const float* g2  = (const float*)d_in[12];
    const float* be2 = (const float*)d_in[13];
    const float* W3  = (const float*)d_in[14];
    const float* b3  = (const float*)d_in[15];
    float* out = (float*)d_out;

    int N = in_sizes[0] / 3;
    if (N > NMAX) N = NMAX;
    int E = in_sizes[1] / 2;

    node_prep<<<(N + 255) / 256, 256>>>(x, W0, b0, ei, N);
    edge_kernel<<<(E + 255) / 256, 256>>>(ei, W1, b1, g1, be1, W2, b2, g2, be2,
                                          W3, b3, g0, be0, out, E);
}

// round 6
// speedup vs baseline: 1.3847x; 1.3600x over previous
#include <cuda_runtime.h>
#include <cstdint>

#define NMAX 100000
#define EPSV 1e-5f
#define KTAN 2.885390081777927f   // 2*log2(e)

typedef unsigned long long ull;

// 16 floats per node: [0..7] = b0 + x@W0_top, [8..15] = x@W0_bot
__device__ float g_nodefeat[NMAX * 16];
__device__ int g_idx_is64;
__device__ __align__(16) float g_staging[208];

// constant params: W1@0, W2@64, b1@128, g1@136, K*be1@144,
//   b2@152, g2@160, K*be2@168, W3@176, g0@184, K*be0@192, b3@200
__constant__ __align__(16) float c_p[208];

// ---------------- f32x2 / MUFU helpers ----------------
__device__ __forceinline__ ull pk2(float lo, float hi) {
    ull d; asm("mov.b64 %0, {%1, %2};" : "=l"(d) : "f"(lo), "f"(hi)); return d;
}
__device__ __forceinline__ ull pkdup(float v) {
    ull d; asm("mov.b64 %0, {%1, %1};" : "=l"(d) : "f"(v)); return d;
}
__device__ __forceinline__ void upk(ull v, float& lo, float& hi) {
    asm("mov.b64 {%0, %1}, %2;" : "=f"(lo), "=f"(hi) : "l"(v));
}
__device__ __forceinline__ ull add2(ull a, ull b) {
    ull d; asm("add.rn.f32x2 %0, %1, %2;" : "=l"(d) : "l"(a), "l"(b)); return d;
}
__device__ __forceinline__ ull mul2(ull a, ull b) {
    ull d; asm("mul.rn.f32x2 %0, %1, %2;" : "=l"(d) : "l"(a), "l"(b)); return d;
}
__device__ __forceinline__ ull fma2(ull a, ull b, ull c) {
    ull d; asm("fma.rn.f32x2 %0, %1, %2, %3;" : "=l"(d) : "l"(a), "l"(b), "l"(c)); return d;
}
__device__ __forceinline__ float ex2f_(float x) {
    float r; asm("ex2.approx.f32 %0, %1;" : "=f"(r) : "f"(x)); return r;
}
__device__ __forceinline__ float rcpf_(float x) {
    float r; asm("rcp.approx.f32 %0, %1;" : "=f"(r) : "f"(x)); return r;
}
__device__ __forceinline__ float rsqf_(float x) {
    float r; asm("rsqrt.approx.f32 %0, %1;" : "=f"(r) : "f"(x)); return r;
}

// ---------------- math blocks (params from __constant__) ----------------

// LayerNorm over 8 packed values -> 8 scalars pre-scaled by KTAN.
// c_p[BOFF..] already holds K*be; K folded into sc.
template<int GOFF, int BOFF>
__device__ __forceinline__ void ln8k(const ull h[4], float u[8]) {
    ull s = add2(add2(h[0], h[1]), add2(h[2], h[3]));
    float sl, sh; upk(s, sl, sh);
    float m = (sl + sh) * 0.125f;

    ull q = mul2(h[0], h[0]);
    q = fma2(h[1], h[1], q);
    q = fma2(h[2], h[2], q);
    q = fma2(h[3], h[3], q);
    float ql, qh; upk(q, ql, qh);
    float msq = (ql + qh) * 0.125f;
    float var = fmaf(-m, m, msq);
    float sc = KTAN * rsqf_(var + EPSV);

    ull sc2 = pkdup(sc);
    ull nm2 = pkdup(-m);
#pragma unroll
    for (int p = 0; p < 4; p++) {
        float2 gv = *reinterpret_cast<const float2*>(&c_p[GOFF + 2 * p]);
        float2 bv = *reinterpret_cast<const float2*>(&c_p[BOFF + 2 * p]);
        ull ag = mul2(sc2, pk2(gv.x, gv.y));       // K*s*g
        ull c  = fma2(nm2, ag, pk2(bv.x, bv.y));   // K*be - m*K*s*g
        ull r  = fma2(h[p], ag, c);                // K*ln(h)
        upk(r, u[2 * p], u[2 * p + 1]);
    }
}

// tanh from pre-scaled arg u = 2x*log2(e): tanh = 1 - 2*rcp(ex2(u)+1)
__device__ __forceinline__ void tanh8s(const float u[8], float y[8]) {
#pragma unroll
    for (int i = 0; i < 8; i++) {
        float t = ex2f_(u[i]);
        float r = rcpf_(t + 1.0f);
        y[i] = fmaf(-2.0f, r, 1.0f);
    }
}

// Dual-edge 8x8 matmul + bias; each weight load feeds both edges.
template<int WOFF, int BOFF>
__device__ __forceinline__ void mm8s2(const float y0[8], const float y1[8],
                                      ull o0[4], ull o1[4]) {
#pragma unroll
    for (int p = 0; p < 4; p++) {
        float2 b = *reinterpret_cast<const float2*>(&c_p[BOFF + 2 * p]);
        ull bp = pk2(b.x, b.y);
        o0[p] = bp; o1[p] = bp;
    }
#pragma unroll
    for (int k = 0; k < 8; k++) {
        float4 wa = *reinterpret_cast<const float4*>(&c_p[WOFF + 8 * k]);
        float4 wb = *reinterpret_cast<const float4*>(&c_p[WOFF + 8 * k + 4]);
        ull w0 = pk2(wa.x, wa.y), w1 = pk2(wa.z, wa.w);
        ull w2 = pk2(wb.x, wb.y), w3 = pk2(wb.z, wb.w);
        ull h0 = pkdup(y0[k]), h1 = pkdup(y1[k]);
        o0[0] = fma2(h0, w0, o0[0]);  o1[0] = fma2(h1, w0, o1[0]);
        o0[1] = fma2(h0, w1, o0[1]);  o1[1] = fma2(h1, w1, o1[1]);
        o0[2] = fma2(h0, w2, o0[2]);  o1[2] = fma2(h1, w2, o1[2]);
        o0[3] = fma2(h0, w3, o0[3]);  o1[3] = fma2(h1, w3, o1[3]);
    }
}

// ---------------- kernel 0: param staging (pre-transformed) ----------------
__global__ void prep_params(const float* __restrict__ W1, const float* __restrict__ b1,
                            const float* __restrict__ g1, const float* __restrict__ be1,
                            const float* __restrict__ W2, const float* __restrict__ b2,
                            const float* __restrict__ g2, const float* __restrict__ be2,
                            const float* __restrict__ W3, const float* __restrict__ b3,
                            const float* __restrict__ g0, const float* __restrict__ be0) {
    int t = threadIdx.x;
    if (t < 64) {
        g_staging[t] = W1[t];
    } else if (t < 128) {
        g_staging[t] = W2[t - 64];
    } else if (t < 208) {
        int i = t - 128, grp = i >> 3, j = i & 7;
        float v;
        switch (grp) {
            case 0: v = b1[j];          break;
            case 1: v = g1[j];          break;
            case 2: v = KTAN * be1[j];  break;
            case 3: v = b2[j];          break;
            case 4: v = g2[j];          break;
            case 5: v = KTAN * be2[j];  break;
            case 6: v = W3[j];          break;
            case 7: v = g0[j];          break;
            case 8: v = KTAN * be0[j];  break;
            default: v = (j == 0) ? b3[0] : 0.0f; break;
        }
        g_staging[128 + i] = v;
    }
}

// ---------------- kernel 1: node precompute + dtype detection ----------------
__global__ void node_prep(const float* __restrict__ x, const float* __restrict__ W0,
                          const float* __restrict__ b0, const void* __restrict__ ei,
                          int N) {
    __shared__ int s_ok;
    if (blockIdx.x == 0) {
        if (threadIdx.x == 0) s_ok = 1;
        __syncthreads();
        long long v = ((const long long*)ei)[threadIdx.x];
        if (v < 0 || v >= (long long)N) s_ok = 0;   // benign race: all write 0
        __syncthreads();
        if (threadIdx.x == 0) g_idx_is64 = s_ok;
    }

    int n = blockIdx.x * blockDim.x + threadIdx.x;
    if (n >= N) return;
    float x0 = x[n * 3 + 0], x1 = x[n * 3 + 1], x2 = x[n * 3 + 2];
    float t[16];
#pragma unroll
    for (int j = 0; j < 8; j++) {
        t[j]     = b0[j] + x0 * W0[j] + x1 * W0[8 + j] + x2 * W0[16 + j];
        t[8 + j] =         x0 * W0[24 + j] + x1 * W0[32 + j] + x2 * W0[40 + j];
    }
    float4* dst = reinterpret_cast<float4*>(g_nodefeat + (size_t)n * 16);
#pragma unroll
    for (int q = 0; q < 4; q++)
        dst[q] = make_float4(t[4 * q], t[4 * q + 1], t[4 * q + 2], t[4 * q + 3]);
}

// ---------------- kernel 2: per-edge MLP, 2 edges/thread ----------------
__global__ __launch_bounds__(256)
void edge_kernel(const void* __restrict__ ei_raw, float* __restrict__ out, int E) {
    int t = blockIdx.x * blockDim.x + threadIdx.x;
    int e0 = 2 * t;
    if (e0 >= E) return;
    bool has2 = (e0 + 1 < E);
    bool vec = has2 && ((E & 1) == 0);   // alignment of the d-side vector load

    int s0, d0, s1, d1;
    if (g_idx_is64) {
        const long long* ei = (const long long*)ei_raw;
        if (vec) {
            longlong2 sv = reinterpret_cast<const longlong2*>(ei)[t];
            longlong2 dv = *reinterpret_cast<const longlong2*>(ei + E + e0);
            s0 = (int)sv.x; s1 = (int)sv.y;
            d0 = (int)dv.x; d1 = (int)dv.y;
        } else {
            s0 = (int)ei[e0]; d0 = (int)ei[E + e0];
            s1 = s0; d1 = d0;
        }
    } else {
        const int* ei = (const int*)ei_raw;
        if (vec) {
            int2 sv = reinterpret_cast<const int2*>(ei)[t];
            int2 dv = *reinterpret_cast<const int2*>(ei + E + e0);
            s0 = sv.x; s1 = sv.y;
            d0 = dv.x; d1 = dv.y;
        } else {
            s0 = ei[e0]; d0 = ei[E + e0];
            s1 = s0; d1 = d0;
        }
    }

    const ulonglong2* nf = reinterpret_cast<const ulonglong2*>(g_nodefeat);
    ulonglong2 a00 = nf[s0 * 4 + 0];
    ulonglong2 a01 = nf[s0 * 4 + 1];
    ulonglong2 c00 = nf[d0 * 4 + 2];
    ulonglong2 c01 = nf[d0 * 4 + 3];
    ulonglong2 a10 = nf[s1 * 4 + 0];
    ulonglong2 a11 = nf[s1 * 4 + 1];
    ulonglong2 c10 = nf[d1 * 4 + 2];
    ulonglong2 c11 = nf[d1 * 4 + 3];

    ull h0[4], h1[4];
    h0[0] = add2(a00.x, c00.x);  h1[0] = add2(a10.x, c10.x);
    h0[1] = add2(a00.y, c00.y);  h1[1] = add2(a10.y, c10.y);
    h0[2] = add2(a01.x, c01.x);  h1[2] = add2(a11.x, c11.x);
    h0[3] = add2(a01.y, c01.y);  h1[3] = add2(a11.y, c11.y);

    float u0[8], u1[8], y0[8], y1[8];
    ln8k<184, 192>(h0, u0);  ln8k<184, 192>(h1, u1);   // g0, K*be0
    tanh8s(u0, y0);          tanh8s(u1, y1);

    ull p0[4], p1[4];
    mm8s2<0, 128>(y0, y1, p0, p1);                     // W1, b1
    ln8k<136, 144>(p0, u0);  ln8k<136, 144>(p1, u1);   // g1, K*be1
    tanh8s(u0, y0);          tanh8s(u1, y1);

    mm8s2<64, 152>(y0, y1, p0, p1);                    // W2, b2
    ln8k<160, 168>(p0, u0);  ln8k<160, 168>(p1, u1);   // g2, K*be2
    tanh8s(u0, y0);          tanh8s(u1, y1);

    float acc0 = c_p[200], acc1 = c_p[200];            // b3
#pragma unroll
    for (int i = 0; i < 8; i++) {
        float w = c_p[176 + i];
        acc0 = fmaf(y0[i], w, acc0);
        acc1 = fmaf(y1[i], w, acc1);
    }
    if (vec) {
        *reinterpret_cast<float2*>(out + e0) = make_float2(acc0, acc1);
    } else {
        out[e0] = acc0;
        if (has2) out[e0 + 1] = acc1;
    }
}

// ---------------- launch ----------------
extern "C" void kernel_launch(void* const* d_in, const int* in_sizes, int n_in,
                              void* d_out, int out_size) {
    const float* x   = (const float*)d_in[0];
    const void*  ei  = (const void*)d_in[1];
    const float* W0  = (const float*)d_in[2];
    const float* b0  = (const float*)d_in[3];
    const float* g0  = (const float*)d_in[4];
    const float* be0 = (const float*)d_in[5];
    const float* W1  = (const float*)d_in[6];
    const float* b1  = (const float*)d_in[7];
    const float* g1  = (const float*)d_in[8];
    const float* be1 = (const float*)d_in[9];
    const float* W2  = (const float*)d_in[10];
    const float* b2  = (const float*)d_in[11];
    const float* g2  = (const float*)d_in[12];
    const float* be2 = (const float*)d_in[13];
    const float* W3  = (const float*)d_in[14];
    const float* b3  = (const float*)d_in[15];
    float* out = (float*)d_out;

    int N = in_sizes[0] / 3;
    if (N > NMAX) N = NMAX;
    int E = in_sizes[1] / 2;

    prep_params<<<1, 256>>>(W1, b1, g1, be1, W2, b2, g2, be2, W3, b3, g0, be0);

    void* staging_ptr = nullptr;
    cudaGetSymbolAddress(&staging_ptr, g_staging);
    cudaMemcpyToSymbolAsync(c_p, staging_ptr, 208 * sizeof(float), 0,
                            cudaMemcpyDeviceToDevice);

    node_prep<<<(N + 255) / 256, 256>>>(x, W0, b0, ei, N);

    int threads = (E + 1) / 2;
    edge_kernel<<<(threads + 255) / 256, 256>>>(ei, out, E);
}

// round 9
// speedup vs baseline: 1.3998x; 1.0109x over previous
#include <cuda_runtime.h>
#include <cstdint>

#define NMAX 100000
#define EPSV 1e-5f
#define KTAN 2.885390081777927f   // 2*log2(e)

typedef unsigned long long ull;

// 16 floats per node: [0..7] = b0 + x@W0_top, [8..15] = x@W0_bot
__device__ float g_nodefeat[NMAX * 16];
__device__ int g_idx_is64;
__device__ __align__(16) float g_staging[208];

// constant params: W1@0, W2@64, b1@128, g1@136, K*be1@144,
//   b2@152, g2@160, K*be2@168, W3@176, g0@184, K*be0@192, b3@200
__constant__ __align__(16) float c_p[208];

// ---------------- f32x2 / MUFU helpers ----------------
__device__ __forceinline__ ull pk2(float lo, float hi) {
    ull d; asm("mov.b64 %0, {%1, %2};" : "=l"(d) : "f"(lo), "f"(hi)); return d;
}
__device__ __forceinline__ ull pkdup(float v) {
    ull d; asm("mov.b64 %0, {%1, %1};" : "=l"(d) : "f"(v)); return d;
}
__device__ __forceinline__ void upk(ull v, float& lo, float& hi) {
    asm("mov.b64 {%0, %1}, %2;" : "=f"(lo), "=f"(hi) : "l"(v));
}
__device__ __forceinline__ ull add2(ull a, ull b) {
    ull d; asm("add.rn.f32x2 %0, %1, %2;" : "=l"(d) : "l"(a), "l"(b)); return d;
}
__device__ __forceinline__ ull mul2(ull a, ull b) {
    ull d; asm("mul.rn.f32x2 %0, %1, %2;" : "=l"(d) : "l"(a), "l"(b)); return d;
}
__device__ __forceinline__ ull fma2(ull a, ull b, ull c) {
    ull d; asm("fma.rn.f32x2 %0, %1, %2, %3;" : "=l"(d) : "l"(a), "l"(b), "l"(c)); return d;
}
__device__ __forceinline__ float ex2f_(float x) {
    float r; asm("ex2.approx.f32 %0, %1;" : "=f"(r) : "f"(x)); return r;
}
__device__ __forceinline__ float rcpf_(float x) {
    float r; asm("rcp.approx.f32 %0, %1;" : "=f"(r) : "f"(x)); return r;
}
__device__ __forceinline__ float rsqf_(float x) {
    float r; asm("rsqrt.approx.f32 %0, %1;" : "=f"(r) : "f"(x)); return r;
}
__device__ __forceinline__ ull shfl_xor_ull(ull v) {
    float a, b; upk(v, a, b);
    a = __shfl_xor_sync(0xffffffffu, a, 1);
    b = __shfl_xor_sync(0xffffffffu, b, 1);
    return pk2(a, b);
}
__device__ __forceinline__ ull sel_ull(bool p, ull a, ull b) { return p ? a : b; }

// ---------------- math blocks (params from __constant__) ----------------

// LayerNorm over 8 packed values -> 8 scalars pre-scaled by KTAN.
template<int GOFF, int BOFF>
__device__ __forceinline__ void ln8k(const ull h[4], float u[8]) {
    ull s = add2(add2(h[0], h[1]), add2(h[2], h[3]));
    float sl, sh; upk(s, sl, sh);
    float m = (sl + sh) * 0.125f;

    ull q = mul2(h[0], h[0]);
    q = fma2(h[1], h[1], q);
    q = fma2(h[2], h[2], q);
    q = fma2(h[3], h[3], q);
    float ql, qh; upk(q, ql, qh);
    float msq = (ql + qh) * 0.125f;
    float var = fmaf(-m, m, msq);
    float sc = KTAN * rsqf_(var + EPSV);

    ull sc2 = pkdup(sc);
    ull nm2 = pkdup(-m);
#pragma unroll
    for (int p = 0; p < 4; p++) {
        float2 gv = *reinterpret_cast<const float2*>(&c_p[GOFF + 2 * p]);
        float2 bv = *reinterpret_cast<const float2*>(&c_p[BOFF + 2 * p]);
        ull ag = mul2(sc2, pk2(gv.x, gv.y));       // K*s*g
        ull c  = fma2(nm2, ag, pk2(bv.x, bv.y));   // K*be - m*K*s*g
        ull r  = fma2(h[p], ag, c);                // K*ln(h)
        upk(r, u[2 * p], u[2 * p + 1]);
    }
}

// tanh from pre-scaled arg u = 2x*log2(e): tanh = 1 - 2*rcp(ex2(u)+1)
__device__ __forceinline__ void tanh8s(const float u[8], float y[8]) {
#pragma unroll
    for (int i = 0; i < 8; i++) {
        float t = ex2f_(u[i]);
        float r = rcpf_(t + 1.0f);
        y[i] = fmaf(-2.0f, r, 1.0f);
    }
}

// Dual-edge 8x8 matmul + bias; each weight load feeds both edges.
template<int WOFF, int BOFF>
__device__ __forceinline__ void mm8s2(const float y0[8], const float y1[8],
                                      ull o0[4], ull o1[4]) {
#pragma unroll
    for (int p = 0; p < 4; p++) {
        float2 b = *reinterpret_cast<const float2*>(&c_p[BOFF + 2 * p]);
        ull bp = pk2(b.x, b.y);
        o0[p] = bp; o1[p] = bp;
    }
#pragma unroll
    for (int k = 0; k < 8; k++) {
        float4 wa = *reinterpret_cast<const float4*>(&c_p[WOFF + 8 * k]);
        float4 wb = *reinterpret_cast<const float4*>(&c_p[WOFF + 8 * k + 4]);
        ull w0 = pk2(wa.x, wa.y), w1 = pk2(wa.z, wa.w);
        ull w2 = pk2(wb.x, wb.y), w3 = pk2(wb.z, wb.w);
        ull h0 = pkdup(y0[k]), h1 = pkdup(y1[k]);
        o0[0] = fma2(h0, w0, o0[0]);  o1[0] = fma2(h1, w0, o1[0]);
        o0[1] = fma2(h0, w1, o0[1]);  o1[1] = fma2(h1, w1, o1[1]);
        o0[2] = fma2(h0, w2, o0[2]);  o1[2] = fma2(h1, w2, o1[2]);
        o0[3] = fma2(h0, w3, o0[3]);  o1[3] = fma2(h1, w3, o1[3]);
    }
}

// ---------------- kernel 1: node precompute + dtype detect + param staging ----
__global__ void node_prep(const float* __restrict__ x, const float* __restrict__ W0,
                          const float* __restrict__ b0, const void* __restrict__ ei,
                          const float* __restrict__ W1, const float* __restrict__ b1,
                          const float* __restrict__ g1, const float* __restrict__ be1,
                          const float* __restrict__ W2, const float* __restrict__ b2,
                          const float* __restrict__ g2, const float* __restrict__ be2,
                          const float* __restrict__ W3, const float* __restrict__ b3,
                          const float* __restrict__ g0, const float* __restrict__ be0,
                          int N) {
    __shared__ int s_ok;
    if (blockIdx.x == 0) {
        if (threadIdx.x == 0) s_ok = 1;
        __syncthreads();
        long long v = ((const long long*)ei)[threadIdx.x];
        if (v < 0 || v >= (long long)N) s_ok = 0;   // benign race: all write 0
        __syncthreads();
        if (threadIdx.x == 0) g_idx_is64 = s_ok;
    } else if (blockIdx.x == 1) {
        int t = threadIdx.x;
        if (t < 64) {
            g_staging[t] = W1[t];
        } else if (t < 128) {
            g_staging[t] = W2[t - 64];
        } else if (t < 208) {
            int i = t - 128, grp = i >> 3, j = i & 7;
            float v;
            switch (grp) {
                case 0: v = b1[j];          break;
                case 1: v = g1[j];          break;
                case 2: v = KTAN * be1[j];  break;
                case 3: v = b2[j];          break;
                case 4: v = g2[j];          break;
                case 5: v = KTAN * be2[j];  break;
                case 6: v = W3[j];          break;
                case 7: v = g0[j];          break;
                case 8: v = KTAN * be0[j];  break;
                default: v = (j == 0) ? b3[0] : 0.0f; break;
            }
            g_staging[128 + i] = v;
        }
    }

    int n = blockIdx.x * blockDim.x + threadIdx.x;
    if (n >= N) return;
    float x0 = x[n * 3 + 0], x1 = x[n * 3 + 1], x2 = x[n * 3 + 2];
    float t[16];
#pragma unroll
    for (int j = 0; j < 8; j++) {
        t[j]     = b0[j] + x0 * W0[j] + x1 * W0[8 + j] + x2 * W0[16 + j];
        t[8 + j] =         x0 * W0[24 + j] + x1 * W0[32 + j] + x2 * W0[40 + j];
    }
    float4* dst = reinterpret_cast<float4*>(g_nodefeat + (size_t)n * 16);
#pragma unroll
    for (int q = 0; q < 4; q++)
        dst[q] = make_float4(t[4 * q], t[4 * q + 1], t[4 * q + 2], t[4 * q + 3]);
}

// ---------------- kernel 2: per-edge MLP, 2 edges/thread, pair-coop gather ----
// Lanes 2i and 2i+1 cooperate: each gather instruction targets ONE 32B node
// region per pair, split 16B/16B by lane parity -> one 128B line per pair
// per instruction (half the L1 wavefronts of the naive gather).
__global__ __launch_bounds__(256)
void edge_kernel(const void* __restrict__ ei_raw, float* __restrict__ out, int E) {
    int t = blockIdx.x * blockDim.x + threadIdx.x;
    int par = threadIdx.x & 1;
    int e0 = 2 * t, e1 = e0 + 1;
    int Em1 = E - 1;
    int ce0 = min(e0, Em1), ce1 = min(e1, Em1);

    int s0, d0, s1, d1;
    if (g_idx_is64) {
        const long long* ei = (const long long*)ei_raw;
        s0 = (int)ei[ce0];     s1 = (int)ei[ce1];
        d0 = (int)ei[E + ce0]; d1 = (int)ei[E + ce1];
    } else {
        const int* ei = (const int*)ei_raw;
        s0 = ei[ce0];     s1 = ei[ce1];
        d0 = ei[E + ce0]; d1 = ei[E + ce1];
    }

    const unsigned m = 0xffffffffu;
    int s0p = __shfl_xor_sync(m, s0, 1), d0p = __shfl_xor_sync(m, d0, 1);
    int s1p = __shfl_xor_sync(m, s1, 1), d1p = __shfl_xor_sync(m, d1, 1);

    // pair-uniform region bases: even-lane's edges (A..D), odd-lane's (Ap..Dp)
    int A  = par ? s0p : s0;
    int B  = par ? d0p : d0;
    int C  = par ? s1p : s1;
    int D  = par ? d1p : d1;
    int Ap = par ? s0  : s0p;
    int Bp = par ? d0  : d0p;
    int Cp = par ? s1  : s1p;
    int Dp = par ? d1  : d1p;

    const ulonglong2* nf = reinterpret_cast<const ulonglong2*>(g_nodefeat);
    // region = node*64B; top half at +0, bot half at +32; my 16B slice at +par*16
    ulonglong2 L0 = nf[4 * A  + par];        // even-edge0 s-top slice
    ulonglong2 L1 = nf[4 * B  + 2 + par];    // even-edge0 d-bot slice
    ulonglong2 L2 = nf[4 * C  + par];        // even-edge1 s-top slice
    ulonglong2 L3 = nf[4 * D  + 2 + par];
    ulonglong2 L4 = nf[4 * Ap + par];        // odd-edge0 s-top slice
    ulonglong2 L5 = nf[4 * Bp + 2 + par];
    ulonglong2 L6 = nf[4 * Cp + par];
    ulonglong2 L7 = nf[4 * Dp + 2 + par];

    // combine top+bot BEFORE exchange (halves the shuffled data)
    ull hA0 = add2(L0.x, L1.x), hA1 = add2(L0.y, L1.y);   // even-edge0, my-par half
    ull hB0 = add2(L2.x, L3.x), hB1 = add2(L2.y, L3.y);   // even-edge1
    ull hC0 = add2(L4.x, L5.x), hC1 = add2(L4.y, L5.y);   // odd-edge0
    ull hD0 = add2(L6.x, L7.x), hD1 = add2(L6.y, L7.y);   // odd-edge1

    // exchange the halves that belong to the partner's edges
    ull ex0 = sel_ull(par, hA0, hC0), ex1 = sel_ull(par, hA1, hC1);
    ull ex2_ = sel_ull(par, hB0, hD0), ex3 = sel_ull(par, hB1, hD1);
    ull r0 = shfl_xor_ull(ex0), r1 = shfl_xor_ull(ex1);
    ull r2 = shfl_xor_ull(ex2_), r3 = shfl_xor_ull(ex3);

    // assemble full h for MY edges: [lo half (j0-3), hi half (j4-7)]
    ull h0[4], h1[4];
    h0[0] = sel_ull(par, r0, hA0);  h0[1] = sel_ull(par, r1, hA1);
    h0[2] = sel_ull(par, hC0, r0);  h0[3] = sel_ull(par, hC1, r1);
    h1[0] = sel_ull(par, r2, hB0);  h1[1] = sel_ull(par, r3, hB1);
    h1[2] = sel_ull(par, hD0, r2);  h1[3] = sel_ull(par, hD1, r3);

    float u0[8], u1[8], y0[8], y1[8];
    ln8k<184, 192>(h0, u0);  ln8k<184, 192>(h1, u1);   // g0, K*be0
    tanh8s(u0, y0);          tanh8s(u1, y1);

    ull p0[4], p1[4];
    mm8s2<0, 128>(y0, y1, p0, p1);                     // W1, b1
    ln8k<136, 144>(p0, u0);  ln8k<136, 144>(p1, u1);   // g1, K*be1
    tanh8s(u0, y0);          tanh8s(u1, y1);

    mm8s2<64, 152>(y0, y1, p0, p1);                    // W2, b2
    ln8k<160, 168>(p0, u0);  ln8k<160, 168>(p1, u1);   // g2, K*be2
    tanh8s(u0, y0);          tanh8s(u1, y1);

    float acc0 = c_p[200], acc1 = c_p[200];            // b3
#pragma unroll
    for (int i = 0; i < 8; i++) {
        float w = c_p[176 + i];
        acc0 = fmaf(y0[i], w, acc0);
        acc1 = fmaf(y1[i], w, acc1);
    }
    if (e1 < E) {
        *reinterpret_cast<float2*>(out + e0) = make_float2(acc0, acc1);
    } else if (e0 < E) {
        out[e0] = acc0;
    }
}

// ---------------- launch ----------------
extern "C" void kernel_launch(void* const* d_in, const int* in_sizes, int n_in,
                              void* d_out, int out_size) {
    const float* x   = (const float*)d_in[0];
    const void*  ei  = (const void*)d_in[1];
    const float* W0  = (const float*)d_in[2];
    const float* b0  = (const float*)d_in[3];
    const float* g0  = (const float*)d_in[4];
    const float* be0 = (const float*)d_in[5];
    const float* W1  = (const float*)d_in[6];
    const float* b1  = (const float*)d_in[7];
    const float* g1  = (const float*)d_in[8];
    const float* be1 = (const float*)d_in[9];
    const float* W2  = (const float*)d_in[10];
    const float* b2  = (const float*)d_in[11];
    const float* g2  = (const float*)d_in[12];
    const float* be2 = (const float*)d_in[13];
    const float* W3  = (const float*)d_in[14];
    const float* b3  = (const float*)d_in[15];
    float* out = (float*)d_out;

    int N = in_sizes[0] / 3;
    if (N > NMAX) N = NMAX;
    int E = in_sizes[1] / 2;

    int nblocks = (N + 255) / 256;
    if (nblocks < 2) nblocks = 2;
    node_prep<<<nblocks, 256>>>(x, W0, b0, ei, W1, b1, g1, be1,
                                W2, b2, g2, be2, W3, b3, g0, be0, N);

    void* staging_ptr = nullptr;
    cudaGetSymbolAddress(&staging_ptr, g_staging);
    cudaMemcpyToSymbolAsync(c_p, staging_ptr, 208 * sizeof(float), 0,
                            cudaMemcpyDeviceToDevice);

    int threads = (E + 1) / 2;
    edge_kernel<<<(threads + 255) / 256, 256>>>(ei, out, E);
}